// round 1
// baseline (speedup 1.0000x reference)
#include <cuda_runtime.h>
#include <cuda_bf16.h>

// Problem constants
#define NROWS 32768
#define DIMK  512
#define NCB   16      // num codebooks
#define CS    256     // codebook size

// GEMM tiling
#define BM 64
#define BN 256
#define BK 32
#define TPB 256

// scratch for argmax indexes (allowed: __device__ global array)
__device__ int g_idx[NROWS * NCB];

__device__ __forceinline__ unsigned long long dup2(float a) {
    unsigned long long r;
    unsigned u = __float_as_uint(a);
    asm("mov.b64 %0, {%1, %1};" : "=l"(r) : "r"(u));
    return r;
}

__device__ __forceinline__ void ffma2(unsigned long long& d,
                                      unsigned long long a,
                                      unsigned long long b) {
    // packed dual fp32 FMA (Blackwell sm_100+): d.lo = a.lo*b.lo + d.lo ; hi likewise
    asm("fma.rn.f32x2 %0, %1, %2, %0;" : "+l"(d) : "l"(a), "l"(b));
}

// ---------------------------------------------------------------------------
// Kernel 1: fused logits GEMM + per-codebook argmax.
// grid = (NROWS/BM, NCB), block = 256 threads.
// Each block: 64 rows x one full codebook (256 columns), K = 512.
// Thread (tx = lane, ty = warp): rows ty*8..ty*8+7, col pairs {2tx+64j, 2tx+64j+1}, j<4.
// ---------------------------------------------------------------------------
__global__ __launch_bounds__(TPB)
void enc_argmax_kernel(const float* __restrict__ x,
                       const float* __restrict__ W,
                       const float* __restrict__ bias,
                       int* __restrict__ gidx)
{
    const int cb   = blockIdx.y;
    const int row0 = blockIdx.x * BM;
    const int tid  = threadIdx.x;
    const int tx   = tid & 31;
    const int ty   = tid >> 5;

    // sA: [row][k], stride 36 floats (conflict-free stores, aligned float4 loads)
    // sB: [k][col^swz(k)], swz(k) = ((k>>2)&7)<<2  (conflict-free both directions)
    __shared__ float sA[BM * 36];          // 9216 B
    __shared__ float sB[BK * BN];          // 32768 B

    unsigned long long acc[8][4];
    #pragma unroll
    for (int i = 0; i < 8; ++i)
        #pragma unroll
        for (int j = 0; j < 4; ++j) acc[i][j] = 0ULL;

    const float* xg = x + (size_t)row0 * DIMK;
    const float* Wg = W + (size_t)cb * CS * DIMK;

    // prefetch registers
    float4 pa[2];   // A tile: 64x32 = 512 float4 / 256 thr = 2 each
    float4 pb[8];   // B tile: 256x32 = 2048 float4 / 256 thr = 8 each

    // ---- load tile 0 ----
    #pragma unroll
    for (int e = 0; e < 2; ++e) {
        int f = tid + TPB * e;
        int r = f >> 3, kq = f & 7;
        pa[e] = *reinterpret_cast<const float4*>(&xg[(size_t)r * DIMK + kq * 4]);
    }
    #pragma unroll
    for (int e = 0; e < 8; ++e) {
        int f = tid + TPB * e;
        int c = f >> 3, kq = f & 7;
        pb[e] = *reinterpret_cast<const float4*>(&Wg[(size_t)c * DIMK + kq * 4]);
    }
    // store tile 0
    #pragma unroll
    for (int e = 0; e < 2; ++e) {
        int f = tid + TPB * e;
        int r = f >> 3, kq = f & 7;
        *reinterpret_cast<float4*>(&sA[r * 36 + kq * 4]) = pa[e];
    }
    #pragma unroll
    for (int e = 0; e < 8; ++e) {
        int f = tid + TPB * e;
        int c = f >> 3, kq = f & 7;
        int swz = kq << 2;                      // ((k>>2)&7)<<2 with k=4kq+u
        sB[(4 * kq + 0) * BN + (c ^ swz)] = pb[e].x;
        sB[(4 * kq + 1) * BN + (c ^ swz)] = pb[e].y;
        sB[(4 * kq + 2) * BN + (c ^ swz)] = pb[e].z;
        sB[(4 * kq + 3) * BN + (c ^ swz)] = pb[e].w;
    }
    __syncthreads();

    const int NT = DIMK / BK;   // 16
    for (int kt = 0; kt < NT; ++kt) {
        // prefetch next tile from global
        if (kt + 1 < NT) {
            const float* xg2 = xg + (kt + 1) * BK;
            const float* Wg2 = Wg + (kt + 1) * BK;
            #pragma unroll
            for (int e = 0; e < 2; ++e) {
                int f = tid + TPB * e;
                int r = f >> 3, kq = f & 7;
                pa[e] = *reinterpret_cast<const float4*>(&xg2[(size_t)r * DIMK + kq * 4]);
            }
            #pragma unroll
            for (int e = 0; e < 8; ++e) {
                int f = tid + TPB * e;
                int c = f >> 3, kq = f & 7;
                pb[e] = *reinterpret_cast<const float4*>(&Wg2[(size_t)c * DIMK + kq * 4]);
            }
        }

        // ---- compute over this BK tile ----
        #pragma unroll
        for (int k4 = 0; k4 < 8; ++k4) {
            float4 av[8];
            #pragma unroll
            for (int i = 0; i < 8; ++i)
                av[i] = *reinterpret_cast<const float4*>(&sA[(ty * 8 + i) * 36 + (k4 << 2)]);
            #pragma unroll
            for (int kk = 0; kk < 4; ++kk) {
                const int k  = (k4 << 2) + kk;
                const int sw = (k4 & 7) << 2;
                const float* sbk = sB + k * BN;
                unsigned long long b2[4];
                #pragma unroll
                for (int j = 0; j < 4; ++j)
                    b2[j] = *reinterpret_cast<const unsigned long long*>(
                        sbk + ((((tx << 1) + (j << 6))) ^ sw));
                #pragma unroll
                for (int i = 0; i < 8; ++i) {
                    float a = (kk == 0) ? av[i].x : (kk == 1) ? av[i].y
                             : (kk == 2) ? av[i].z : av[i].w;
                    unsigned long long a2 = dup2(a);
                    #pragma unroll
                    for (int j = 0; j < 4; ++j) ffma2(acc[i][j], a2, b2[j]);
                }
            }
        }
        __syncthreads();

        if (kt + 1 < NT) {
            #pragma unroll
            for (int e = 0; e < 2; ++e) {
                int f = tid + TPB * e;
                int r = f >> 3, kq = f & 7;
                *reinterpret_cast<float4*>(&sA[r * 36 + kq * 4]) = pa[e];
            }
            #pragma unroll
            for (int e = 0; e < 8; ++e) {
                int f = tid + TPB * e;
                int c = f >> 3, kq = f & 7;
                int swz = kq << 2;
                sB[(4 * kq + 0) * BN + (c ^ swz)] = pb[e].x;
                sB[(4 * kq + 1) * BN + (c ^ swz)] = pb[e].y;
                sB[(4 * kq + 2) * BN + (c ^ swz)] = pb[e].z;
                sB[(4 * kq + 3) * BN + (c ^ swz)] = pb[e].w;
            }
            __syncthreads();
        }
    }

    // ---- bias + argmax (per row: warp-wide reduce over 256 cols) ----
    float bl[8];
    #pragma unroll
    for (int j = 0; j < 4; ++j) {
        int c = (tx << 1) + (j << 6);
        bl[2 * j + 0] = __ldg(&bias[cb * CS + c]);
        bl[2 * j + 1] = __ldg(&bias[cb * CS + c + 1]);
    }

    #pragma unroll
    for (int i = 0; i < 8; ++i) {
        float bv = -3.402823466e38f;
        int   bc = 0x7fffffff;
        #pragma unroll
        for (int j = 0; j < 4; ++j) {
            unsigned long long u = acc[i][j];
            float lo = __uint_as_float((unsigned)u);
            float hi = __uint_as_float((unsigned)(u >> 32));
            int c0 = (tx << 1) + (j << 6);
            float l0 = lo + bl[2 * j + 0];
            float l1 = hi + bl[2 * j + 1];
            if (l0 > bv || (l0 == bv && c0 < bc))     { bv = l0; bc = c0; }
            if (l1 > bv || (l1 == bv && c0 + 1 < bc)) { bv = l1; bc = c0 + 1; }
        }
        // warp reduction, tie -> smaller index (matches jnp.argmax first-max)
        #pragma unroll
        for (int off = 16; off; off >>= 1) {
            float ov = __shfl_xor_sync(0xffffffffu, bv, off);
            int   oc = __shfl_xor_sync(0xffffffffu, bc, off);
            if (ov > bv || (ov == bv && oc < bc)) { bv = ov; bc = oc; }
        }
        if (tx == 0)
            gidx[(row0 + ty * 8 + i) * NCB + cb] = bc;
    }
}

// ---------------------------------------------------------------------------
// Kernel 2: decode — gather 16 centers per row, sum, scale.
// grid = NROWS blocks x 128 threads; each thread owns one float4 of the row.
// ---------------------------------------------------------------------------
__global__ __launch_bounds__(128)
void dec_gather_kernel(const float* __restrict__ centers,
                       const int* __restrict__ gidx,
                       const float* __restrict__ centers_scale,
                       float* __restrict__ out)
{
    __shared__ int   sidx[NCB];
    __shared__ float sscale;
    const int row = blockIdx.x;
    const int tid = threadIdx.x;

    if (tid < NCB) sidx[tid] = gidx[row * NCB + tid];
    if (tid == 0)  sscale = expf(10.0f * centers_scale[0]);
    __syncthreads();

    float4 s = make_float4(0.f, 0.f, 0.f, 0.f);
    #pragma unroll
    for (int c = 0; c < NCB; ++c) {
        const float4* p = reinterpret_cast<const float4*>(
            centers + ((size_t)((c << 8) + sidx[c])) * DIMK);
        float4 v = __ldg(&p[tid]);
        s.x += v.x; s.y += v.y; s.z += v.z; s.w += v.w;
    }
    float sc = sscale;
    s.x *= sc; s.y *= sc; s.z *= sc; s.w *= sc;
    reinterpret_cast<float4*>(out)[(size_t)row * (DIMK / 4) + tid] = s;
}

// ---------------------------------------------------------------------------
// launch
// inputs: 0=x (32768*512 f32), 1=W (4096*512 f32), 2=b (4096 f32),
//         3=centers (16*256*512 f32), 4=logits_scale (1 f32, unused: argmax-invariant),
//         5=centers_scale (1 f32)
// ---------------------------------------------------------------------------
extern "C" void kernel_launch(void* const* d_in, const int* in_sizes, int n_in,
                              void* d_out, int out_size)
{
    const float* x       = (const float*)d_in[0];
    const float* W       = (const float*)d_in[1];
    const float* b       = (const float*)d_in[2];
    const float* centers = (const float*)d_in[3];
    const float* cscale  = (const float*)d_in[5];
    float* out           = (float*)d_out;

    int* gidx_ptr = nullptr;
    cudaGetSymbolAddress((void**)&gidx_ptr, g_idx);

    dim3 grid1(NROWS / BM, NCB);
    enc_argmax_kernel<<<grid1, TPB>>>(x, W, b, gidx_ptr);

    dec_gather_kernel<<<NROWS, 128>>>(centers, gidx_ptr, cscale, out);
}